// round 8
// baseline (speedup 1.0000x reference)
#include <cuda_runtime.h>
#include <cuda_bf16.h>
#include <cstdint>

// BiLSTM-CRF forward, all fp32 (Viterbi argmax stability forbids low precision).
// f32x2 packed FMA; persistent recurrence: thread-private full-k GEMV rows,
// smem-resident Whh, register c-state, ld.cg h streaming, no intra-step syncs.
//
// Shapes: V=50000 E=512 H=512 HD=1024 B=64 L=512 T=16, START=14 STOP=15

#define NEGV -10000.0f

typedef unsigned long long u64;

// ---------------- scratch (__device__ globals) ----------------------------
__device__ float g_G[(size_t)32768 * 4096];       // input-proj gates [l*64+b][dir*2048+g*512+h]
__device__ float g_Wt[(size_t)512 * 4096];        // Wih^T combined  [k][n]
__device__ float g_WhT[2][(size_t)512 * 2048];    // Whh^T per dir   [k][g*512+h]
__device__ float g_hT[2][2][64][512];             // [parity][dir][b][k]  (k contiguous)
__device__ float g_hrow[(size_t)32768 * 1024];    // [l*64+b][dir*512+h]
__device__ float g_feats[(size_t)64 * 512 * 16];  // [b][l][t]
__device__ unsigned g_bar[2];                     // per-dir step barrier

// ---------------- helpers ---------------------------------------------------
__device__ __forceinline__ void ffma2(u64 &d, u64 a, u64 b) {
    asm("fma.rn.f32x2 %0, %1, %2, %0;" : "+l"(d) : "l"(a), "l"(b));
}
__device__ __forceinline__ u64 pack2(float x) {
    u64 r; asm("mov.b64 %0, {%1, %1};" : "=l"(r) : "f"(x)); return r;
}
__device__ __forceinline__ float2 unpack2(u64 v) {
    float2 f; asm("mov.b64 {%0, %1}, %2;" : "=f"(f.x), "=f"(f.y) : "l"(v)); return f;
}
__device__ __forceinline__ float sigf(float x) { return 1.0f / (1.0f + expf(-x)); }

__device__ __forceinline__ void cp16(unsigned dst_sm, const float* src) {
    asm volatile("cp.async.cg.shared.global [%0], [%1], 16;\n" :: "r"(dst_sm), "l"(src));
}
template <int N> __device__ __forceinline__ void cp_wait() {
    asm volatile("cp.async.wait_group %0;\n" :: "n"(N) : "memory");
}
__device__ __forceinline__ void cp_commit() {
    asm volatile("cp.async.commit_group;\n" ::: "memory");
}
__device__ __forceinline__ void bar_arrive(unsigned* p) {
    asm volatile("red.release.gpu.global.add.u32 [%0], %1;" :: "l"(p), "r"(1u) : "memory");
}
__device__ __forceinline__ unsigned ld_acq(const unsigned* p) {
    unsigned v; asm volatile("ld.acquire.gpu.global.u32 %0, [%1];" : "=r"(v) : "l"(p) : "memory");
    return v;
}

// ---------------- prep kernels ---------------------------------------------
__global__ void prepA(const float* __restrict__ wf, const float* __restrict__ wb,
                      const float* __restrict__ h0) {
    int idx = blockIdx.x * 256 + threadIdx.x;
    if (idx < 2) g_bar[idx] = 0;
    if (idx < 2097152) {                       // 512*4096
        int k = idx >> 12, n = idx & 4095;
        g_Wt[idx] = (n < 2048) ? wf[n * 512 + k] : wb[(n - 2048) * 512 + k];
    } else {
        int r2 = idx - 2097152;                // 2*64*512: straight copy (same layout)
        if (r2 < 65536) ((float*)g_hT)[r2] = h0[r2];
    }
}
__global__ void prepB(const float* __restrict__ whf, const float* __restrict__ whb) {
    int idx = blockIdx.x * 256 + threadIdx.x;  // 2*512*2048
    int dir = idx >> 20; int r = idx & ((1 << 20) - 1);
    int k = r >> 11, n = r & 2047;
    const float* w = dir ? whb : whf;
    g_WhT[dir][(size_t)k * 2048 + n] = w[n * 512 + k];
}

// ---------------- input projection GEMM (cp.async 2-stage) ------------------
__global__ void __launch_bounds__(256) gemm1(const int* __restrict__ sent,
                                             const float* __restrict__ embed,
                                             const float* __restrict__ bf,
                                             const float* __restrict__ bb) {
    __shared__ float As[2][128][16];
    __shared__ float Bs[2][16][128];
    __shared__ int toks[128];
    int tid = threadIdx.x;
    int n0 = blockIdx.x * 128;
    int m0 = blockIdx.y * 128;
    if (tid < 128) { int m = m0 + tid; toks[tid] = sent[(m & 63) * 512 + (m >> 6)]; }
    __syncthreads();
    int tx = tid & 15, ty = tid >> 4;
    unsigned smA = (unsigned)__cvta_generic_to_shared(&As[0][0][0]);
    unsigned smB = (unsigned)__cvta_generic_to_shared(&Bs[0][0][0]);

    u64 acc[8][4];
#pragma unroll
    for (int i = 0; i < 8; i++)
#pragma unroll
        for (int j = 0; j < 4; j++) acc[i][j] = 0ull;

    auto issue = [&](int k0, int buf) {
#pragma unroll
        for (int r = 0; r < 2; r++) {
            int idx = tid * 2 + r;
            int am = idx >> 2, aq = idx & 3;
            cp16(smA + (unsigned)(((buf * 128 + am) * 16 + aq * 4) * 4),
                 embed + (size_t)toks[am] * 512 + k0 + aq * 4);
            int bk = idx >> 5, bn = idx & 31;
            cp16(smB + (unsigned)(((buf * 16 + bk) * 128 + bn * 4) * 4),
                 g_Wt + (size_t)(k0 + bk) * 4096 + n0 + bn * 4);
        }
        cp_commit();
    };

    issue(0, 0);
    for (int c = 0; c < 32; c++) {
        cp_wait<0>();
        __syncthreads();
        if (c < 31) issue((c + 1) * 16, (c + 1) & 1);
        const int buf = c & 1;
#pragma unroll
        for (int k = 0; k < 16; k++) {
            u64 bv[4];
#pragma unroll
            for (int j = 0; j < 4; j++)
                bv[j] = *(const u64*)&Bs[buf][k][(j * 16 + tx) * 2];
#pragma unroll
            for (int i = 0; i < 8; i++) {
                u64 av = pack2(As[buf][ty * 8 + i][k]);
#pragma unroll
                for (int j = 0; j < 4; j++) ffma2(acc[i][j], av, bv[j]);
            }
        }
    }
#pragma unroll
    for (int j = 0; j < 4; j++) {
        int n = n0 + (j * 16 + tx) * 2;
        float2 bias;
        bias.x = (n < 2048) ? bf[n] : bb[n - 2048];
        bias.y = (n + 1 < 2048) ? bf[n + 1] : bb[n + 1 - 2048];
#pragma unroll
        for (int i = 0; i < 8; i++) {
            float2 v = unpack2(acc[i][j]);
            size_t row = (size_t)(m0 + ty * 8 + i);
            *(float2*)&g_G[row * 4096 + n] = make_float2(v.x + bias.x, v.y + bias.y);
        }
    }
}

// ---------------- persistent LSTM recurrence --------------------------------
// 128 blocks = 2 dirs x 64 h-tiles (8 h-cols). 256 threads: thread = (b, h-pair),
// owns 2 cells x 4 gates over full k=512. Whh slice smem-resident; h streamed
// with ld.cg float4; G prefetched to registers; c-state in registers.
__global__ void __launch_bounds__(256, 1) lstm_persist(const float* __restrict__ c0) {
    extern __shared__ float Ws[];    // [512][32] : k*32 + hp*8 + g*2 + ci
    const int tid = threadIdx.x;
    const int dir = blockIdx.x >> 6;
    const int h0  = (blockIdx.x & 63) * 8;
    const int b   = tid >> 2;        // 0..63 (warp = 8 consecutive b)
    const int hp  = tid & 3;         // 0..3

    const float* Wd = g_WhT[dir];
    for (int i = tid; i < 16384; i += 256) {
        int k = i >> 5, c = i & 31;
        Ws[i] = Wd[(size_t)k * 2048 + ((c >> 1) & 3) * 512 + h0 + 2 * (c >> 3) + (c & 1)];
    }
    float creg[2];
    creg[0] = c0[((size_t)dir * 64 + b) * 512 + h0 + 2 * hp];
    creg[1] = c0[((size_t)dir * 64 + b) * 512 + h0 + 2 * hp + 1];
    __syncthreads();

    const float* wbase = Ws + hp * 8;

    for (int t = 0; t < 512; t++) {
        const int p = t & 1;
        const int l = dir ? (511 - t) : t;

        // G prefetch into registers (used ~8K cycles later)
        const float* Gp = g_G + ((size_t)l * 64 + b) * 4096 + (size_t)dir * 2048 + h0 + 2 * hp;
        float2 gI = __ldcg((const float2*)(Gp));
        float2 gF = __ldcg((const float2*)(Gp + 512));
        float2 gGt = __ldcg((const float2*)(Gp + 1024));
        float2 gO = __ldcg((const float2*)(Gp + 1536));

        const float4* hrow = (const float4*)(&g_hT[p][dir][b][0]);
        u64 acc[4] = {0ull, 0ull, 0ull, 0ull};

        for (int kg = 0; kg < 128; kg += 4) {
            float4 hv[4];
#pragma unroll
            for (int i = 0; i < 4; i++) hv[i] = __ldcg(hrow + kg + i);
#pragma unroll
            for (int i = 0; i < 4; i++) {
                const float hs[4] = {hv[i].x, hv[i].y, hv[i].z, hv[i].w};
#pragma unroll
                for (int j = 0; j < 4; j++) {
                    const int k = (kg + i) * 4 + j;
                    u64 a = pack2(hs[j]);
                    ulonglong2 wA = *(const ulonglong2*)(wbase + k * 32);
                    ulonglong2 wB = *(const ulonglong2*)(wbase + k * 32 + 4);
                    ffma2(acc[0], a, wA.x);
                    ffma2(acc[1], a, wA.y);
                    ffma2(acc[2], a, wB.x);
                    ffma2(acc[3], a, wB.y);
                }
            }
        }

        // fused LSTM pointwise
        float2 s0 = unpack2(acc[0]), s1 = unpack2(acc[1]);
        float2 s2 = unpack2(acc[2]), s3 = unpack2(acc[3]);
        float hcell[2];
#pragma unroll
        for (int ci = 0; ci < 2; ci++) {
            float iv = (ci ? s0.y : s0.x) + (ci ? gI.y : gI.x);
            float fv = (ci ? s1.y : s1.x) + (ci ? gF.y : gF.x);
            float gv = (ci ? s2.y : s2.x) + (ci ? gGt.y : gGt.x);
            float ov = (ci ? s3.y : s3.x) + (ci ? gO.y : gO.x);
            float cn = sigf(fv) * creg[ci] + sigf(iv) * tanhf(gv);
            creg[ci] = cn;
            hcell[ci] = sigf(ov) * tanhf(cn);
        }
        *(float2*)&g_hrow[((size_t)l * 64 + b) * 1024 + dir * 512 + h0 + 2 * hp] =
            make_float2(hcell[0], hcell[1]);
        *(float2*)&g_hT[p ^ 1][dir][b][h0 + 2 * hp] = make_float2(hcell[0], hcell[1]);

        // per-dir grid barrier
        if (t != 511) {
            __syncthreads();
            if (tid == 0) {
                bar_arrive(&g_bar[dir]);
                unsigned target = 64u * (unsigned)(t + 1);
                while (ld_acq(&g_bar[dir]) < target) { }
            }
            __syncthreads();
        }
    }
}

// ---------------- tag projection ---------------------------------------------
__global__ void __launch_bounds__(256) feats_kernel(const float* __restrict__ Wtag,
                                                    const float* __restrict__ btag) {
    int idx = blockIdx.x * 256 + threadIdx.x;   // 64*512*16
    int t = idx & 15;
    int l = (idx >> 4) & 511;
    int b = idx >> 13;
    const float4* hr = (const float4*)(g_hrow + (size_t)(l * 64 + b) * 1024);
    const float4* wr = (const float4*)(Wtag + (size_t)t * 1024);
    float a0 = 0.f, a1 = 0.f;
#pragma unroll 8
    for (int k = 0; k < 256; k += 2) {
        float4 x = hr[k],     w = wr[k];
        float4 y = hr[k + 1], v = wr[k + 1];
        a0 += x.x * w.x + x.y * w.y + x.z * w.z + x.w * w.w;
        a1 += y.x * v.x + y.y * v.y + y.z * v.z + y.w * v.w;
    }
    g_feats[((size_t)b * 512 + l) * 16 + t] = a0 + a1 + btag[t];
}

// ---------------- Viterbi -----------------------------------------------------
__global__ void __launch_bounds__(32) viterbi_kernel(const float* __restrict__ trans,
                                                     float* __restrict__ out) {
    int b = blockIdx.x;
    int lane = threadIdx.x;
    __shared__ unsigned char bp[512][16];
    __shared__ float smax[16];
    bool active = lane < 16;
    int row = active ? lane : 15;
    float tr[16];
#pragma unroll
    for (int j = 0; j < 16; j++) tr[j] = trans[row * 16 + j];
    float fv = (lane == 14) ? 0.0f : NEGV;   // START=14

    const float* fb = g_feats + (size_t)b * 512 * 16;
    for (int l = 0; l < 512; l++) {
        float best = -3.4e38f;
        int arg = 0;
#pragma unroll
        for (int j = 0; j < 16; j++) {
            float s = __shfl_sync(0xffffffffu, fv, j) + tr[j];
            if (s > best) { best = s; arg = j; }
        }
        float nf = best + fb[l * 16 + row];
        if (active) bp[l][lane] = (unsigned char)arg;
        fv = nf;
    }
    float term = fv + trans[15 * 16 + row];  // STOP=15
    if (active) smax[lane] = term;
    __syncwarp();
    if (lane == 0) {
        float best = smax[0]; int tag = 0;
        for (int j = 1; j < 16; j++) if (smax[j] > best) { best = smax[j]; tag = j; }
        out[b] = best;
        for (int l = 511; l >= 0; l--) {
            out[64 + b * 512 + l] = (float)tag;
            tag = bp[l][tag];
        }
    }
}

// ---------------- launch -------------------------------------------------------
extern "C" void kernel_launch(void* const* d_in, const int* in_sizes, int n_in,
                              void* d_out, int out_size) {
    const int*   sent  = (const int*)d_in[0];
    const float* embed = (const float*)d_in[1];
    const float* Wih_f = (const float*)d_in[2];
    const float* Whh_f = (const float*)d_in[3];
    const float* b_f   = (const float*)d_in[4];
    const float* Wih_b = (const float*)d_in[5];
    const float* Whh_b = (const float*)d_in[6];
    const float* b_b   = (const float*)d_in[7];
    const float* h0    = (const float*)d_in[8];
    const float* c0    = (const float*)d_in[9];
    const float* W_tag = (const float*)d_in[10];
    const float* b_tag = (const float*)d_in[11];
    const float* trans = (const float*)d_in[12];
    float* out = (float*)d_out;

    cudaFuncSetAttribute(lstm_persist, cudaFuncAttributeMaxDynamicSharedMemorySize, 65536);

    prepA<<<8448, 256>>>(Wih_f, Wih_b, h0);               // launch 1
    prepB<<<8192, 256>>>(Whh_f, Whh_b);                   // launch 2
    gemm1<<<dim3(32, 256), 256>>>(sent, embed, b_f, b_b);  // launch 3
    lstm_persist<<<128, 256, 65536>>>(c0);                // launch 4
    feats_kernel<<<2048, 256>>>(W_tag, b_tag);            // launch 5
    viterbi_kernel<<<64, 32>>>(trans, out);               // launch 6
}